// round 2
// baseline (speedup 1.0000x reference)
#include <cuda_runtime.h>
#include <math.h>

#define NN    2048
#define BG    8
#define NODES (NN*BG)
#define KNNK  4
#define INC   16
#define HIDD  128
#define NC    64

// ---------------- scratch (no allocs allowed) ----------------
__device__ float g_xw1[NODES*HIDD];
__device__ float g_h1 [NODES*HIDD];
__device__ float g_xw2[NODES*HIDD];
__device__ float g_h2 [NODES*HIDD];
__device__ float g_pool[BG*NC*HIDD];
__device__ float g_ss [BG*NC*NC];
__device__ float g_ca [BG*NC];
__device__ float g_ssum[BG*NC];
__device__ float g_tr [BG];
__device__ int   g_cnt [NODES];
__device__ int   g_ecnt[BG];
__device__ int   g_knn [NODES*KNNK];

// ---------------- kernels ----------------
__global__ void k_zero() {
    int i = blockIdx.x*blockDim.x + threadIdx.x;
    if (i < NODES) g_cnt[i] = 0;
    if (i < BG) { g_ecnt[i] = 0; g_tr[i] = 0.f; }
}

// in-degree histogram (original edges) + per-graph edge counts
__global__ void k_hist(const int* __restrict__ src, const int* __restrict__ dst, int E) {
    int e = blockIdx.x*blockDim.x + threadIdx.x;
    if (e < E) {
        atomicAdd(&g_cnt[dst[e]], 1);
        atomicAdd(&g_ecnt[src[e]/NN], 1);
    }
}

// xw1 = x @ W1   ([16384,16]@[16,128])
__global__ void k_xw1(const float* __restrict__ x, const float* __restrict__ W1) {
    __shared__ float xr[INC];
    int n = blockIdx.x, c = threadIdx.x;
    if (c < INC) xr[c] = x[n*INC + c];
    __syncthreads();
    float a = 0.f;
#pragma unroll
    for (int k = 0; k < INC; k++) a += xr[k] * W1[k*HIDD + c];
    g_xw1[n*HIDD + c] = a;
}

// self-loop term: h1[n] = xw1[n] / deg[n]   (deg = in-degree + 1)
__global__ void k_self1() {
    int n = blockIdx.x, c = threadIdx.x;
    float inv = 1.f / (float)(g_cnt[n] + 1);
    g_h1[n*HIDD + c] = g_xw1[n*HIDD + c] * inv;
}

// edge scatter: h1[dst] += xw1[src] * rsqrt(deg_s)*rsqrt(deg_d)
__global__ void k_scatter1(const int* __restrict__ src, const int* __restrict__ dst) {
    int e = blockIdx.x;
    int s = src[e], d = dst[e];
    float norm = rsqrtf((float)(g_cnt[s] + 1)) * rsqrtf((float)(g_cnt[d] + 1));
    int c = threadIdx.x;
    atomicAdd(&g_h1[d*HIDD + c], g_xw1[s*HIDD + c] * norm);
}

__global__ void k_relu1(const float* __restrict__ b1) {
    int n = blockIdx.x, c = threadIdx.x;
    float v = g_h1[n*HIDD + c] + b1[c];
    g_h1[n*HIDD + c] = fmaxf(v, 0.f);
}

// kNN (K=4) on h1[:, :3] per graph, tie-break toward lower index (matches top_k)
__global__ void k_knn() {
    __shared__ float cx[NN], cy[NN], cz[NN];
    int b = blockIdx.x, base = b*NN;
    for (int j = threadIdx.x; j < NN; j += blockDim.x) {
        const float* r = &g_h1[(base + j)*HIDD];
        cx[j] = r[0]; cy[j] = r[1]; cz[j] = r[2];
    }
    __syncthreads();
    int i = blockIdx.y*blockDim.x + threadIdx.x;
    float xi = cx[i], yi = cy[i], zi = cz[i];
    float bd[KNNK]; int bi[KNNK];
#pragma unroll
    for (int t = 0; t < KNNK; t++) { bd[t] = 1e30f; bi[t] = NN; }
    for (int j = 0; j < NN; j++) {
        if (j == i) continue;
        float dx = xi - cx[j], dy = yi - cy[j], dz = zi - cz[j];
        float d2 = dx*dx + dy*dy + dz*dz;
        if (d2 < bd[3]) {
            bd[3] = d2; bi[3] = j;
#pragma unroll
            for (int t = 3; t > 0; t--) {
                if (bd[t] < bd[t-1]) {
                    float td = bd[t]; bd[t] = bd[t-1]; bd[t-1] = td;
                    int ti = bi[t]; bi[t] = bi[t-1]; bi[t-1] = ti;
                }
            }
        }
    }
#pragma unroll
    for (int t = 0; t < KNNK; t++) g_knn[(base + i)*KNNK + t] = base + bi[t];
}

// xw2 = h1 @ W2   ([16384,128]@[128,128]) — 16 rows per block
__global__ void k_xw2(const float* __restrict__ W2) {
    __shared__ float As[16][HIDD];
    int r0 = blockIdx.x * 16, c = threadIdx.x;
    for (int r = 0; r < 16; r++) As[r][c] = g_h1[(r0 + r)*HIDD + c];
    __syncthreads();
    float acc[16];
#pragma unroll
    for (int r = 0; r < 16; r++) acc[r] = 0.f;
    for (int k = 0; k < HIDD; k++) {
        float bv = W2[k*HIDD + c];
#pragma unroll
        for (int r = 0; r < 16; r++) acc[r] += As[r][k] * bv;
    }
    for (int r = 0; r < 16; r++) g_xw2[(r0 + r)*HIDD + c] = acc[r];
}

// GCN2: deg==5 everywhere -> norm = rsqrt(5)^2 on every term incl. self-loop
__global__ void k_gcn2(const float* __restrict__ b2) {
    int n = blockIdx.x, c = threadIdx.x;
    float nf = rsqrtf(5.0f); nf = nf * nf;
    int k0 = g_knn[n*KNNK+0], k1 = g_knn[n*KNNK+1], k2 = g_knn[n*KNNK+2], k3 = g_knn[n*KNNK+3];
    float v = g_xw2[n*HIDD+c]*nf + g_xw2[k0*HIDD+c]*nf + g_xw2[k1*HIDD+c]*nf
            + g_xw2[k2*HIDD+c]*nf + g_xw2[k3*HIDD+c]*nf;
    v += b2[c];
    g_h2[n*HIDD + c] = fmaxf(v, 0.f);
}

// s = softmax(h2 @ Wp + bp) over 64 clusters; one block (64 thr) per node
__global__ void k_s(const float* __restrict__ Wp, const float* __restrict__ bp,
                    float* __restrict__ sout) {
    __shared__ float hr[HIDD];
    __shared__ float red[NC];
    int n = blockIdx.x, c = threadIdx.x;
    hr[c] = g_h2[n*HIDD + c];
    hr[c + NC] = g_h2[n*HIDD + c + NC];
    __syncthreads();
    float a = bp[c];
#pragma unroll 8
    for (int k = 0; k < HIDD; k++) a += hr[k] * Wp[k*NC + c];
    red[c] = a; __syncthreads();
    for (int o = 32; o; o >>= 1) { if (c < o) red[c] = fmaxf(red[c], red[c+o]); __syncthreads(); }
    float mx = red[0]; __syncthreads();
    float e = expf(a - mx);
    red[c] = e; __syncthreads();
    for (int o = 32; o; o >>= 1) { if (c < o) red[c] += red[c+o]; __syncthreads(); }
    sout[n*NC + c] = e / red[0];
}

// pooled[b,c,f] = sum_n s[b,n,c]*h2[b,n,f] ; grid (8 graphs, 8 c-groups), 128 thr (f)
__global__ void k_pool(const float* __restrict__ s) {
    __shared__ float ssm[128][8];
    int b = blockIdx.x, cg = blockIdx.y, f = threadIdx.x;
    int base = b*NN;
    float acc[8];
#pragma unroll
    for (int j = 0; j < 8; j++) acc[j] = 0.f;
    for (int nt = 0; nt < NN; nt += 128) {
#pragma unroll
        for (int j = 0; j < 8; j++) ssm[f][j] = s[(base + nt + f)*NC + cg*8 + j];
        __syncthreads();
#pragma unroll 4
        for (int nn = 0; nn < 128; nn++) {
            float xv = g_h2[(base + nt + nn)*HIDD + f];
#pragma unroll
            for (int j = 0; j < 8; j++) acc[j] += ssm[nn][j] * xv;
        }
        __syncthreads();
    }
#pragma unroll
    for (int j = 0; j < 8; j++) g_pool[(b*NC + cg*8 + j)*HIDD + f] = acc[j];
}

// ss[b,c,d] = sum_n s[b,n,c]*s[b,n,d] ; grid (8, 8 c-groups), 64 thr (d)
__global__ void k_ssk(const float* __restrict__ s) {
    __shared__ float ssm[128][8];
    int b = blockIdx.x, cg = blockIdx.y, d = threadIdx.x;
    int base = b*NN;
    float acc[8];
#pragma unroll
    for (int j = 0; j < 8; j++) acc[j] = 0.f;
    for (int nt = 0; nt < NN; nt += 128) {
        for (int r = d; r < 128; r += NC)
#pragma unroll
            for (int j = 0; j < 8; j++) ssm[r][j] = s[(base + nt + r)*NC + cg*8 + j];
        __syncthreads();
#pragma unroll 4
        for (int nn = 0; nn < 128; nn++) {
            float xv = s[(base + nt + nn)*NC + d];
#pragma unroll
            for (int j = 0; j < 8; j++) acc[j] += ssm[nn][j] * xv;
        }
        __syncthreads();
    }
#pragma unroll
    for (int j = 0; j < 8; j++) g_ss[b*NC*NC + (cg*8 + j)*NC + d] = acc[j];
}

// ca[b,c] = sum_n s*deg ; ssum[b,c] = sum_n s   (deg = in-degree count, no +1)
__global__ void k_ca(const float* __restrict__ s) {
    int b = blockIdx.x, c = threadIdx.x;
    int base = b*NN;
    float ca = 0.f, su = 0.f;
#pragma unroll 8
    for (int n = 0; n < NN; n++) {
        float sv = s[(base + n)*NC + c];
        ca += sv * (float)g_cnt[base + n];
        su += sv;
    }
    g_ca[b*NC + c] = ca; g_ssum[b*NC + c] = su;
}

// trace(S^T A S) per graph = sum over edges of dot(s[src], s[dst]); warp per edge
__global__ void k_tr(const int* __restrict__ src, const int* __restrict__ dst,
                     const float* __restrict__ s, int E) {
    __shared__ float bins[BG];
    if (threadIdx.x < BG) bins[threadIdx.x] = 0.f;
    __syncthreads();
    int warp = threadIdx.x >> 5, lane = threadIdx.x & 31;
    int gw = blockIdx.x*(blockDim.x >> 5) + warp;
    int nw = gridDim.x*(blockDim.x >> 5);
    for (int e = gw; e < E; e += nw) {
        int a = src[e], d = dst[e];
        float v = s[a*NC + lane]*s[d*NC + lane] + s[a*NC + 32 + lane]*s[d*NC + 32 + lane];
#pragma unroll
        for (int o = 16; o; o >>= 1) v += __shfl_down_sync(0xffffffffu, v, o);
        if (lane == 0) atomicAdd(&bins[a/NN], v);
    }
    __syncthreads();
    if (threadIdx.x < BG) atomicAdd(&g_tr[threadIdx.x], bins[threadIdx.x]);
}

// selu + log_softmax over f; one block per (b,c) row
__global__ void k_out(float* __restrict__ out) {
    __shared__ float red[HIDD];
    int row = blockIdx.x, f = threadIdx.x;
    float v = g_pool[row*HIDD + f];
    const float alpha = 1.6732632423543772f, scale = 1.0507009873554805f;
    v = scale * (v > 0.f ? v : alpha * expm1f(v));
    red[f] = v; __syncthreads();
    for (int o = 64; o; o >>= 1) { if (f < o) red[f] = fmaxf(red[f], red[f+o]); __syncthreads(); }
    float mx = red[0]; __syncthreads();
    float e = expf(v - mx);
    red[f] = e; __syncthreads();
    for (int o = 64; o; o >>= 1) { if (f < o) red[f] += red[f+o]; __syncthreads(); }
    float lse = logf(red[0]);
    out[row*HIDD + f] = v - mx - lse;
}

// scalar loss = mean(spectral) + mean(ortho) + mean(cluster)
__global__ void k_final(float* __restrict__ loss_out) {
    __shared__ float red[256];
    int t = threadIdx.x;
    float spectral = 0.f, ortho = 0.f, cluster = 0.f;
    for (int b = 0; b < BG; b++) {
        // Frobenius norm of ss
        float p = 0.f;
        for (int i = t; i < NC*NC; i += 256) { float v = g_ss[b*NC*NC + i]; p += v*v; }
        red[t] = p; __syncthreads();
        for (int o = 128; o; o >>= 1) { if (t < o) red[t] += red[t+o]; __syncthreads(); }
        float fro = sqrtf(red[0]); __syncthreads();
        // || ss/fro - I/8 ||_F
        p = 0.f;
        for (int i = t; i < NC*NC; i += 256) {
            float v = g_ss[b*NC*NC + i] / fro;
            if ((i >> 6) == (i & 63)) v -= 0.125f;
            p += v*v;
        }
        red[t] = p; __syncthreads();
        for (int o = 128; o; o >>= 1) { if (t < o) red[t] += red[t+o]; __syncthreads(); }
        ortho += sqrtf(red[0]); __syncthreads();
        // sum ca^2
        p = 0.f;
        for (int i = t; i < NC; i += 256) { float v = g_ca[b*NC + i]; p += v*v; }
        red[t] = p; __syncthreads();
        for (int o = 128; o; o >>= 1) { if (t < o) red[t] += red[t+o]; __syncthreads(); }
        float ca2 = red[0]; __syncthreads();
        float m = 0.5f * (float)g_ecnt[b];
        spectral += -(g_tr[b] - ca2 / (2.f*m)) / (2.f*m);
        // || ssum ||_2
        p = 0.f;
        for (int i = t; i < NC; i += 256) { float v = g_ssum[b*NC + i]; p += v*v; }
        red[t] = p; __syncthreads();
        for (int o = 128; o; o >>= 1) { if (t < o) red[t] += red[t+o]; __syncthreads(); }
        cluster += sqrtf(red[0]) / (float)NN * 8.f - 1.f; __syncthreads();
    }
    if (t == 0)
        loss_out[0] = spectral / (float)BG + ortho / (float)BG + cluster / (float)BG;
}

// ---------------- launch ----------------
extern "C" void kernel_launch(void* const* d_in, const int* in_sizes, int n_in,
                              void* d_out, int out_size) {
    const float* x    = (const float*)d_in[0];
    const int*   esrc = (const int*)  d_in[1];
    const int*   edst = (const int*)  d_in[2];
    const float* W1   = (const float*)d_in[4];
    const float* b1   = (const float*)d_in[5];
    const float* W2   = (const float*)d_in[6];
    const float* b2   = (const float*)d_in[7];
    const float* Wp   = (const float*)d_in[8];
    const float* bp   = (const float*)d_in[9];
    float* out = (float*)d_out;
    int E = in_sizes[1];

    float* loss_out = out + BG*NC*HIDD;        // [65536]
    float* sout     = out + BG*NC*HIDD + 1;    // [65537 ..)

    k_zero<<<(NODES + 255)/256, 256>>>();
    k_hist<<<(E + 255)/256, 256>>>(esrc, edst, E);
    k_xw1<<<NODES, HIDD>>>(x, W1);
    k_self1<<<NODES, HIDD>>>();
    k_scatter1<<<E, HIDD>>>(esrc, edst);
    k_relu1<<<NODES, HIDD>>>(b1);
    dim3 kg(BG, NN/256);
    k_knn<<<kg, 256>>>();
    k_xw2<<<NODES/16, HIDD>>>(W2);
    k_gcn2<<<NODES, HIDD>>>(b2);
    k_s<<<NODES, NC>>>(Wp, bp, sout);
    dim3 pg(BG, 8);
    k_pool<<<pg, HIDD>>>(sout);
    k_ssk<<<pg, NC>>>(sout);
    k_ca<<<BG, NC>>>(sout);
    k_tr<<<2048, 256>>>(esrc, edst, sout, E);
    k_out<<<BG*NC, HIDD>>>(out);
    k_final<<<1, 256>>>(loss_out);
}

// round 3
// speedup vs baseline: 1.8356x; 1.8356x over previous
#include <cuda_runtime.h>
#include <math.h>

#define NN    2048
#define BG    8
#define NODES (NN*BG)
#define KNNK  4
#define INC   16
#define HIDD  128
#define NC    64
#define EMAX  262144

// ---------------- scratch (no allocs allowed) ----------------
__device__ float g_y  [NODES*HIDD];   // xw1 * rsqrt(deg)
__device__ float g_h1 [NODES*HIDD];
__device__ float g_xw2[NODES*HIDD];
__device__ float g_h2 [NODES*HIDD];
__device__ float g_coord[3*NODES];    // h1[:, 0:3] compact (SoA)
__device__ float g_pool[BG*NC*HIDD];
__device__ float g_ss [BG*NC*NC];
__device__ float g_ca [BG*NC];
__device__ float g_ssum[BG*NC];
__device__ float g_tr [BG];
__device__ int   g_cnt [NODES];
__device__ int   g_rowptr[NODES];
__device__ int   g_pos [NODES];
__device__ int   g_eidx[EMAX];
__device__ int   g_ecnt[BG];
__device__ int   g_knn [NODES*KNNK];

// ---------------- kernels ----------------
__global__ void k_zero() {
    int i = blockIdx.x*blockDim.x + threadIdx.x;
    if (i < NODES) g_cnt[i] = 0;
    if (i < BG*NC*HIDD) g_pool[i] = 0.f;
    if (i < BG*NC*NC) g_ss[i] = 0.f;
    if (i < BG*NC) { g_ca[i] = 0.f; g_ssum[i] = 0.f; }
    if (i < BG) { g_ecnt[i] = 0; g_tr[i] = 0.f; }
}

// in-degree histogram (original edges) + per-graph edge counts
__global__ void k_hist(const int* __restrict__ src, const int* __restrict__ dst, int E) {
    int e = blockIdx.x*blockDim.x + threadIdx.x;
    if (e < E) {
        atomicAdd(&g_cnt[dst[e]], 1);
        atomicAdd(&g_ecnt[src[e]/NN], 1);
    }
}

// exclusive prefix sum of g_cnt -> g_rowptr, g_pos (one block, 1024 thr, 16 each)
__global__ void k_scan() {
    __shared__ int wsum[32];
    int t = threadIdx.x, lane = t & 31, w = t >> 5;
    int base = t*16;
    int loc[16]; int s = 0;
#pragma unroll
    for (int i = 0; i < 16; i++) { loc[i] = s; s += g_cnt[base + i]; }
    int v = s;
#pragma unroll
    for (int o = 1; o < 32; o <<= 1) { int u = __shfl_up_sync(~0u, v, o); if (lane >= o) v += u; }
    if (lane == 31) wsum[w] = v;
    __syncthreads();
    if (w == 0) {
        int u = wsum[lane];
#pragma unroll
        for (int o = 1; o < 32; o <<= 1) { int x = __shfl_up_sync(~0u, u, o); if (lane >= o) u += x; }
        wsum[lane] = u;
    }
    __syncthreads();
    int excl = v - s + (w ? wsum[w-1] : 0);
#pragma unroll
    for (int i = 0; i < 16; i++) { int off = excl + loc[i]; g_rowptr[base+i] = off; g_pos[base+i] = off; }
}

// bucket edges by dst
__global__ void k_fill(const int* __restrict__ src, const int* __restrict__ dst, int E) {
    int e = blockIdx.x*blockDim.x + threadIdx.x;
    if (e < E) {
        int p = atomicAdd(&g_pos[dst[e]], 1);
        g_eidx[p] = src[e];
    }
}

// y = (x @ W1) * rsqrt(deg)   ([16384,16]@[16,128])
__global__ void k_xw1y(const float* __restrict__ x, const float* __restrict__ W1) {
    __shared__ float xr[INC];
    int n = blockIdx.x, c = threadIdx.x;
    if (c < INC) xr[c] = x[n*INC + c];
    __syncthreads();
    float a = 0.f;
#pragma unroll
    for (int k = 0; k < INC; k++) a += xr[k] * W1[k*HIDD + c];
    g_y[n*HIDD + c] = a * rsqrtf((float)(g_cnt[n] + 1));
}

// GCN1 gather: h1[n] = relu(rsqrt(deg)*(y[n] + sum y[src]) + b1); also emit coords
__global__ void k_gcn1(const float* __restrict__ b1) {
    __shared__ int idxs[512];
    int n = blockIdx.x, c = threadIdx.x;
    int beg = g_rowptr[n], cnt = g_cnt[n];
    int lim = cnt < 512 ? cnt : 512;
    for (int i = c; i < lim; i += HIDD) idxs[i] = g_eidx[beg + i];
    __syncthreads();
    float acc = g_y[n*HIDD + c];
#pragma unroll 4
    for (int i = 0; i < lim; i++) acc += g_y[idxs[i]*HIDD + c];
    for (int i = 512; i < cnt; i++) acc += g_y[g_eidx[beg + i]*HIDD + c];
    float v = acc * rsqrtf((float)(cnt + 1)) + b1[c];
    v = fmaxf(v, 0.f);
    g_h1[n*HIDD + c] = v;
    if (c < 3) g_coord[c*NODES + n] = v;
}

// kNN (K=4) on coords per graph; grid (BG, NN/128), 128 thr
__global__ void k_knn() {
    __shared__ float cx[NN], cy[NN], cz[NN];
    int b = blockIdx.x, base = b*NN;
    for (int j = threadIdx.x; j < NN; j += blockDim.x) {
        cx[j] = g_coord[0*NODES + base + j];
        cy[j] = g_coord[1*NODES + base + j];
        cz[j] = g_coord[2*NODES + base + j];
    }
    __syncthreads();
    int i = blockIdx.y*blockDim.x + threadIdx.x;
    float xi = cx[i], yi = cy[i], zi = cz[i];
    float bd[KNNK]; int bi[KNNK];
#pragma unroll
    for (int t = 0; t < KNNK; t++) { bd[t] = 1e30f; bi[t] = NN; }
    for (int j = 0; j < NN; j++) {
        if (j == i) continue;
        float dx = xi - cx[j], dy = yi - cy[j], dz = zi - cz[j];
        float d2 = dx*dx + dy*dy + dz*dz;
        if (d2 < bd[3]) {
            bd[3] = d2; bi[3] = j;
#pragma unroll
            for (int t = 3; t > 0; t--) {
                if (bd[t] < bd[t-1]) {
                    float td = bd[t]; bd[t] = bd[t-1]; bd[t-1] = td;
                    int ti = bi[t]; bi[t] = bi[t-1]; bi[t-1] = ti;
                }
            }
        }
    }
#pragma unroll
    for (int t = 0; t < KNNK; t++) g_knn[(base + i)*KNNK + t] = base + bi[t];
}

// xw2 = h1 @ W2   ([16384,128]@[128,128]) — 16 rows per block
__global__ void k_xw2(const float* __restrict__ W2) {
    __shared__ float As[16][HIDD];
    int r0 = blockIdx.x * 16, c = threadIdx.x;
    for (int r = 0; r < 16; r++) As[r][c] = g_h1[(r0 + r)*HIDD + c];
    __syncthreads();
    float acc[16];
#pragma unroll
    for (int r = 0; r < 16; r++) acc[r] = 0.f;
    for (int k = 0; k < HIDD; k++) {
        float bv = W2[k*HIDD + c];
#pragma unroll
        for (int r = 0; r < 16; r++) acc[r] += As[r][k] * bv;
    }
    for (int r = 0; r < 16; r++) g_xw2[(r0 + r)*HIDD + c] = acc[r];
}

// GCN2: deg==5 everywhere -> norm = rsqrt(5)^2 on every term incl. self-loop
__global__ void k_gcn2(const float* __restrict__ b2) {
    int n = blockIdx.x, c = threadIdx.x;
    float nf = rsqrtf(5.0f); nf = nf * nf;
    int k0 = g_knn[n*KNNK+0], k1 = g_knn[n*KNNK+1], k2 = g_knn[n*KNNK+2], k3 = g_knn[n*KNNK+3];
    float v = g_xw2[n*HIDD+c]*nf + g_xw2[k0*HIDD+c]*nf + g_xw2[k1*HIDD+c]*nf
            + g_xw2[k2*HIDD+c]*nf + g_xw2[k3*HIDD+c]*nf;
    v += b2[c];
    g_h2[n*HIDD + c] = fmaxf(v, 0.f);
}

// s = softmax(h2 @ Wp + bp) over 64 clusters; one block (64 thr) per node
__global__ void k_s(const float* __restrict__ Wp, const float* __restrict__ bp,
                    float* __restrict__ sout) {
    __shared__ float hr[HIDD];
    __shared__ float red[NC];
    int n = blockIdx.x, c = threadIdx.x;
    hr[c] = g_h2[n*HIDD + c];
    hr[c + NC] = g_h2[n*HIDD + c + NC];
    __syncthreads();
    float a = bp[c];
#pragma unroll 8
    for (int k = 0; k < HIDD; k++) a += hr[k] * Wp[k*NC + c];
    red[c] = a; __syncthreads();
    for (int o = 32; o; o >>= 1) { if (c < o) red[c] = fmaxf(red[c], red[c+o]); __syncthreads(); }
    float mx = red[0]; __syncthreads();
    float e = expf(a - mx);
    red[c] = e; __syncthreads();
    for (int o = 32; o; o >>= 1) { if (c < o) red[c] += red[c+o]; __syncthreads(); }
    sout[n*NC + c] = e / red[0];
}

// pooled[b,c,f] += sum over n-chunk of s[b,n,c]*h2[b,n,f]; grid (8,8,4), 128 thr
__global__ void k_pool(const float* __restrict__ s) {
    __shared__ float ssm[128][9];
    int b = blockIdx.x, cg = blockIdx.y, ch = blockIdx.z, f = threadIdx.x;
    int base = b*NN + ch*(NN/4);
    float acc[8];
#pragma unroll
    for (int j = 0; j < 8; j++) acc[j] = 0.f;
    for (int nt = 0; nt < NN/4; nt += 128) {
#pragma unroll
        for (int j = 0; j < 8; j++) ssm[f][j] = s[(base + nt + f)*NC + cg*8 + j];
        __syncthreads();
#pragma unroll 4
        for (int nn = 0; nn < 128; nn++) {
            float xv = g_h2[(base + nt + nn)*HIDD + f];
#pragma unroll
            for (int j = 0; j < 8; j++) acc[j] += ssm[nn][j] * xv;
        }
        __syncthreads();
    }
#pragma unroll
    for (int j = 0; j < 8; j++) atomicAdd(&g_pool[(b*NC + cg*8 + j)*HIDD + f], acc[j]);
}

// ss[b,c,d] += sum over n-chunk of s[b,n,c]*s[b,n,d]; grid (8,8,4), 64 thr
__global__ void k_ssk(const float* __restrict__ s) {
    __shared__ float ssm[128][9];
    int b = blockIdx.x, cg = blockIdx.y, ch = blockIdx.z, d = threadIdx.x;
    int base = b*NN + ch*(NN/4);
    float acc[8];
#pragma unroll
    for (int j = 0; j < 8; j++) acc[j] = 0.f;
    for (int nt = 0; nt < NN/4; nt += 128) {
        for (int r = d; r < 128; r += NC)
#pragma unroll
            for (int j = 0; j < 8; j++) ssm[r][j] = s[(base + nt + r)*NC + cg*8 + j];
        __syncthreads();
#pragma unroll 4
        for (int nn = 0; nn < 128; nn++) {
            float xv = s[(base + nt + nn)*NC + d];
#pragma unroll
            for (int j = 0; j < 8; j++) acc[j] += ssm[nn][j] * xv;
        }
        __syncthreads();
    }
#pragma unroll
    for (int j = 0; j < 8; j++) atomicAdd(&g_ss[b*NC*NC + (cg*8 + j)*NC + d], acc[j]);
}

// ca[b,c] += sum s*deg ; ssum[b,c] += sum s ; grid (8,16), 64 thr
__global__ void k_ca(const float* __restrict__ s) {
    int b = blockIdx.x, ch = blockIdx.y, c = threadIdx.x;
    int base = b*NN + ch*(NN/16);
    float ca = 0.f, su = 0.f;
#pragma unroll 8
    for (int n = 0; n < NN/16; n++) {
        float sv = s[(base + n)*NC + c];
        ca += sv * (float)g_cnt[base + n];
        su += sv;
    }
    atomicAdd(&g_ca[b*NC + c], ca);
    atomicAdd(&g_ssum[b*NC + c], su);
}

// trace(S^T A S) per graph = sum over edges of dot(s[src], s[dst]); warp per edge
__global__ void k_tr(const int* __restrict__ src, const int* __restrict__ dst,
                     const float* __restrict__ s, int E) {
    __shared__ float bins[BG];
    if (threadIdx.x < BG) bins[threadIdx.x] = 0.f;
    __syncthreads();
    int warp = threadIdx.x >> 5, lane = threadIdx.x & 31;
    int gw = blockIdx.x*(blockDim.x >> 5) + warp;
    int nw = gridDim.x*(blockDim.x >> 5);
    for (int e = gw; e < E; e += nw) {
        int a = src[e], d = dst[e];
        float v = s[a*NC + lane]*s[d*NC + lane] + s[a*NC + 32 + lane]*s[d*NC + 32 + lane];
#pragma unroll
        for (int o = 16; o; o >>= 1) v += __shfl_down_sync(0xffffffffu, v, o);
        if (lane == 0) atomicAdd(&bins[a/NN], v);
    }
    __syncthreads();
    if (threadIdx.x < BG) atomicAdd(&g_tr[threadIdx.x], bins[threadIdx.x]);
}

// selu + log_softmax over f; one block per (b,c) row
__global__ void k_out(float* __restrict__ out) {
    __shared__ float red[HIDD];
    int row = blockIdx.x, f = threadIdx.x;
    float v = g_pool[row*HIDD + f];
    const float alpha = 1.6732632423543772f, scale = 1.0507009873554805f;
    v = scale * (v > 0.f ? v : alpha * expm1f(v));
    red[f] = v; __syncthreads();
    for (int o = 64; o; o >>= 1) { if (f < o) red[f] = fmaxf(red[f], red[f+o]); __syncthreads(); }
    float mx = red[0]; __syncthreads();
    float e = expf(v - mx);
    red[f] = e; __syncthreads();
    for (int o = 64; o; o >>= 1) { if (f < o) red[f] += red[f+o]; __syncthreads(); }
    float lse = logf(red[0]);
    out[row*HIDD + f] = v - mx - lse;
}

// scalar loss = mean(spectral) + mean(ortho) + mean(cluster)
__global__ void k_final(float* __restrict__ loss_out) {
    __shared__ float red[256];
    int t = threadIdx.x;
    float spectral = 0.f, ortho = 0.f, cluster = 0.f;
    for (int b = 0; b < BG; b++) {
        float p = 0.f;
        for (int i = t; i < NC*NC; i += 256) { float v = g_ss[b*NC*NC + i]; p += v*v; }
        red[t] = p; __syncthreads();
        for (int o = 128; o; o >>= 1) { if (t < o) red[t] += red[t+o]; __syncthreads(); }
        float fro = sqrtf(red[0]); __syncthreads();
        p = 0.f;
        for (int i = t; i < NC*NC; i += 256) {
            float v = g_ss[b*NC*NC + i] / fro;
            if ((i >> 6) == (i & 63)) v -= 0.125f;
            p += v*v;
        }
        red[t] = p; __syncthreads();
        for (int o = 128; o; o >>= 1) { if (t < o) red[t] += red[t+o]; __syncthreads(); }
        ortho += sqrtf(red[0]); __syncthreads();
        p = 0.f;
        for (int i = t; i < NC; i += 256) { float v = g_ca[b*NC + i]; p += v*v; }
        red[t] = p; __syncthreads();
        for (int o = 128; o; o >>= 1) { if (t < o) red[t] += red[t+o]; __syncthreads(); }
        float ca2 = red[0]; __syncthreads();
        float m = 0.5f * (float)g_ecnt[b];
        spectral += -(g_tr[b] - ca2 / (2.f*m)) / (2.f*m);
        p = 0.f;
        for (int i = t; i < NC; i += 256) { float v = g_ssum[b*NC + i]; p += v*v; }
        red[t] = p; __syncthreads();
        for (int o = 128; o; o >>= 1) { if (t < o) red[t] += red[t+o]; __syncthreads(); }
        cluster += sqrtf(red[0]) / (float)NN * 8.f - 1.f; __syncthreads();
    }
    if (t == 0)
        loss_out[0] = spectral / (float)BG + ortho / (float)BG + cluster / (float)BG;
}

// ---------------- launch ----------------
extern "C" void kernel_launch(void* const* d_in, const int* in_sizes, int n_in,
                              void* d_out, int out_size) {
    const float* x    = (const float*)d_in[0];
    const int*   esrc = (const int*)  d_in[1];
    const int*   edst = (const int*)  d_in[2];
    const float* W1   = (const float*)d_in[4];
    const float* b1   = (const float*)d_in[5];
    const float* W2   = (const float*)d_in[6];
    const float* b2   = (const float*)d_in[7];
    const float* Wp   = (const float*)d_in[8];
    const float* bp   = (const float*)d_in[9];
    float* out = (float*)d_out;
    int E = in_sizes[1];

    float* loss_out = out + BG*NC*HIDD;        // [65536]
    float* sout     = out + BG*NC*HIDD + 1;    // [65537 ..)

    k_zero<<<(BG*NC*HIDD + 255)/256, 256>>>();
    k_hist<<<(E + 255)/256, 256>>>(esrc, edst, E);
    k_scan<<<1, 1024>>>();
    k_fill<<<(E + 255)/256, 256>>>(esrc, edst, E);
    k_xw1y<<<NODES, HIDD>>>(x, W1);
    k_gcn1<<<NODES, HIDD>>>(b1);
    dim3 kg(BG, NN/128);
    k_knn<<<kg, 128>>>();
    k_xw2<<<NODES/16, HIDD>>>(W2);
    k_gcn2<<<NODES, HIDD>>>(b2);
    k_s<<<NODES, NC>>>(Wp, bp, sout);
    dim3 pg(BG, 8, 4);
    k_pool<<<pg, HIDD>>>(sout);
    k_ssk<<<pg, NC>>>(sout);
    dim3 cg(BG, 16);
    k_ca<<<cg, NC>>>(sout);
    k_tr<<<2048, 256>>>(esrc, edst, sout, E);
    k_out<<<BG*NC, HIDD>>>(out);
    k_final<<<1, 256>>>(loss_out);
}